// round 4
// baseline (speedup 1.0000x reference)
#include <cuda_runtime.h>
#include <math.h>

#define S0 3600
#define S1 720
#define S2 144
#define S3 36
#define S4 9

typedef unsigned long long u64;

// ---------------- static device scratch (no runtime allocation) ----------------
__device__ __align__(16) float    g_x  [S0*S0];          // dense scattered input grid (51.8MB)
__device__ __align__(16) unsigned g_p1e[S1*S1*10];       // encoded max-pool accumulators (level1)
__device__ __align__(16) float    g_p1v[S1*S1*10];       // decoded values (0 at inactive)
__device__ __align__(16) int      g_list[S1*S1];         // active cell list at level1
__device__ int      g_cnt;
__device__ __align__(16) unsigned g_p2e[S2*S2*64];
__device__ __align__(16) float    g_p2v[S2*S2*64];
__device__ __align__(16) unsigned g_p3e[S3*S3*128];
__device__ __align__(16) float    g_p3v[S3*S3*128];
__device__ __align__(16) unsigned g_p4e[S4*S4*256];
__device__ __align__(16) float    g_p4v[S4*S4*256];
__device__ float    g_h[32];

// ---------------- helpers ----------------
__device__ __forceinline__ unsigned encf(float f) {
    unsigned u = __float_as_uint(f);
    return (u & 0x80000000u) ? ~u : (u | 0x80000000u);
}
__device__ __forceinline__ float decf(unsigned u) {
    return __uint_as_float((u & 0x80000000u) ? (u & 0x7fffffffu) : ~u);
}
__device__ __forceinline__ float eluf(float x) {
    return x > 0.f ? x : expm1f(x);
}
// packed f32x2 FMA (FFMA2): d = a*b + d  (lanes independent)
__device__ __forceinline__ void fma2(u64& d, u64 a, u64 b) {
    asm("fma.rn.f32x2 %0, %1, %2, %0;" : "+l"(d) : "l"(a), "l"(b));
}
__device__ __forceinline__ u64 pack2(float v) {
    u64 r;
    asm("mov.b64 %0, {%1, %1};" : "=l"(r) : "f"(v));
    return r;
}
__device__ __forceinline__ float2 unpack2(u64 a) {
    float2 r;
    asm("mov.b64 {%0, %1}, %2;" : "=f"(r.x), "=f"(r.y) : "l"(a));
    return r;
}
__device__ __forceinline__ void pool_scatter8(unsigned* d, u64 a0, u64 a1, u64 a2, u64 a3) {
    float2 f;
    f = unpack2(a0); atomicMax(d+0, encf(eluf(f.x))); atomicMax(d+1, encf(eluf(f.y)));
    f = unpack2(a1); atomicMax(d+2, encf(eluf(f.x))); atomicMax(d+3, encf(eluf(f.y)));
    f = unpack2(a2); atomicMax(d+4, encf(eluf(f.x))); atomicMax(d+5, encf(eluf(f.y)));
    f = unpack2(a3); atomicMax(d+6, encf(eluf(f.x))); atomicMax(d+7, encf(eluf(f.y)));
}

// ---------------- K0: zero pool accumulators (grid cleared incrementally) ----------------
__global__ void k_zero() {
    size_t i  = (size_t)blockIdx.x * blockDim.x + threadIdx.x;
    size_t st = (size_t)gridDim.x * blockDim.x;
    uint4 z = make_uint4(0u, 0u, 0u, 0u);
    for (size_t j = i; j < (size_t)(S1*S1*10/4);   j += st) ((uint4*)g_p1e)[j] = z;
    for (size_t j = i; j < (size_t)(S2*S2*64/4);   j += st) ((uint4*)g_p2e)[j] = z;
    for (size_t j = i; j < (size_t)(S3*S3*128/4);  j += st) ((uint4*)g_p3e)[j] = z;
    for (size_t j = i; j < (size_t)(S4*S4*256/4);  j += st) ((uint4*)g_p4e)[j] = z;
    if (i == 0) g_cnt = 0;
}

// ---------------- K1: scatter points onto grid ----------------
__global__ void k_scatter(const int* __restrict__ coords,
                          const float* __restrict__ feat, int P) {
    int p = blockIdx.x * blockDim.x + threadIdx.x;
    if (p >= P) return;
    int r = coords[2*p], c = coords[2*p+1];
    atomicAdd(&g_x[r*S0 + c], feat[p]);   // duplicates add (matches .at[].add)
}

// ---------------- K2: conv1 (1->10) at active sites, fused ELU + maxpool scatter ----------------
__global__ void k_conv1(const int* __restrict__ coords,
                        const float* __restrict__ w1, int P) {
    int p = blockIdx.x * blockDim.x + threadIdx.x;
    if (p >= P) return;
    int r = coords[2*p], c = coords[2*p+1];
    float acc[10];
#pragma unroll
    for (int co = 0; co < 10; co++) acc[co] = 0.f;
#pragma unroll
    for (int dr = -2; dr <= 2; dr++) {
        int rr = r + dr;
        if ((unsigned)rr >= (unsigned)S0) continue;
#pragma unroll
        for (int dc = -2; dc <= 2; dc++) {
            int cc = c + dc;
            if ((unsigned)cc >= (unsigned)S0) continue;
            float v = g_x[rr*S0 + cc];
            if (v != 0.f) {
                int tap = (dr+2)*5 + (dc+2);
#pragma unroll
                for (int co = 0; co < 10; co++) acc[co] += v * w1[tap*10 + co];
            }
        }
    }
    int pc = (r/5)*S1 + (c/5);
    unsigned* dst = &g_p1e[pc*10];
#pragma unroll
    for (int co = 0; co < 10; co++)
        atomicMax(&dst[co], encf(eluf(acc[co])));
}

// ---------------- K3: clear only the scattered cells (grid back to all-zero) ----------------
__global__ void k_clearpts(const int* __restrict__ coords, int P) {
    int p = blockIdx.x * blockDim.x + threadIdx.x;
    if (p >= P) return;
    g_x[coords[2*p]*S0 + coords[2*p+1]] = 0.f;
}

// ---------------- decode encoded pool -> dense values (0 at inactive) ----------------
__global__ void k_decode(int which, int n) {
    const unsigned* e; float* v;
    switch (which) {
        case 0:  e = g_p1e; v = g_p1v; break;
        case 1:  e = g_p2e; v = g_p2v; break;
        case 2:  e = g_p3e; v = g_p3v; break;
        default: e = g_p4e; v = g_p4v; break;
    }
    int i = blockIdx.x * blockDim.x + threadIdx.x;
    if (i >= n) return;
    unsigned u = e[i];
    v[i] = u ? decf(u) : 0.f;
}

// ---------------- build active-cell list (warp-aggregated atomics) ----------------
__global__ void k_list() {
    int i = blockIdx.x * blockDim.x + threadIdx.x;
    bool act = (i < S1*S1) && (g_p1e[i*10] != 0u);
    unsigned m = __ballot_sync(0xffffffffu, act);
    if (!m) return;
    int lane = threadIdx.x & 31;
    int ldr  = __ffs(m) - 1;
    int base = 0;
    if (lane == ldr) base = atomicAdd(&g_cnt, __popc(m));
    base = __shfl_sync(0xffffffffu, base, ldr);
    if (act) g_list[base + __popc(m & ((1u << lane) - 1u))] = i;
}

// ---------------- K4: conv2 (10->64) over active cells, f32x2, fused ELU + pool ----------------
// 256 threads: 32 cells x 8 cog-groups (8 couts each)
__global__ __launch_bounds__(256) void k_conv2(const float* __restrict__ w2) {
    __shared__ float in_s[32*251];
    __shared__ int   cs[32];
    __shared__ int   cv[32];
    int cnt  = g_cnt;
    int base = blockIdx.x * 32;
    if (base >= cnt) return;
    if (threadIdx.x < 32) {
        int idx = base + threadIdx.x;
        int ok  = idx < cnt;
        cs[threadIdx.x] = g_list[ok ? idx : base];
        cv[threadIdx.x] = ok;
    }
    __syncthreads();
    for (int t = threadIdx.x; t < 32*250; t += 256) {
        int j = t / 250, k = t - j*250;
        int tap = k / 10, ci = k - tap*10;
        int id = cs[j];
        int rr = id / S1 + tap/5 - 2;
        int cc = id % S1 + tap%5 - 2;
        float v = 0.f;
        if ((unsigned)rr < (unsigned)S1 && (unsigned)cc < (unsigned)S1)
            v = g_p1v[(rr*S1 + cc)*10 + ci];
        in_s[j*251 + k] = v;
    }
    __syncthreads();
    int cog  = threadIdx.x & 7;            // 8 groups x 8 couts
    int cell = threadIdx.x >> 3;
    const float* ip = &in_s[cell*251];
    const ulonglong2* wq = (const ulonglong2*)w2 + cog*2;  // row = 16 ulonglong2
    u64 a0=0, a1=0, a2=0, a3=0;
#pragma unroll 10
    for (int k = 0; k < 250; k++) {
        u64 vv = pack2(ip[k]);
        ulonglong2 q0 = wq[k*16];
        ulonglong2 q1 = wq[k*16 + 1];
        fma2(a0, vv, q0.x); fma2(a1, vv, q0.y);
        fma2(a2, vv, q1.x); fma2(a3, vv, q1.y);
    }
    if (cv[cell]) {
        int id = cs[cell];
        int pc = ((id/S1)/5)*S2 + (id%S1)/5;
        pool_scatter8(&g_p2e[pc*64 + cog*8], a0, a1, a2, a3);
    }
}

// ---------------- K6: conv3 (64->128) dense over 144^2, f32x2, 2 cells/thread ----------------
// 512 threads: 32 row-pairs (8x8 cell tile) x 16 cog-groups (8 couts each)
__global__ __launch_bounds__(512) void k_conv3(const float* __restrict__ w3) {
    __shared__ float in_s[144*65];         // 12x12 window x 64ch, stride 65 (37.4KB)
    int r0 = blockIdx.y * 8, c0 = blockIdx.x * 8;
    for (int t = threadIdx.x; t < 144*64; t += 512) {
        int pos = t >> 6, ci = t & 63;
        int wr = pos / 12, wc = pos - wr*12;
        int gr = r0 - 2 + wr, gc = c0 - 2 + wc;
        float v = 0.f;
        if ((unsigned)gr < (unsigned)S2 && (unsigned)gc < (unsigned)S2)
            v = g_p2v[(gr*S2 + gc)*64 + ci];
        in_s[pos*65 + ci] = v;
    }
    __syncthreads();
    int cog  = threadIdx.x & 15;           // 16 groups x 8 couts
    int pair = threadIdx.x >> 4;           // 0..31: rows (2pr, 2pr+1), col pc
    int pr = pair >> 3, pc = pair & 7;
    u64 a0=0, a1=0, a2=0, a3=0;            // cell (2pr, pc)
    u64 b0=0, b1=0, b2=0, b3=0;            // cell (2pr+1, pc)
    const ulonglong2* wb = (const ulonglong2*)w3 + cog*2;  // row = 32 ulonglong2
#pragma unroll 1
    for (int tap = 0; tap < 25; tap++) {
        const float* ip0 = &in_s[((2*pr + tap/5)*12 + (pc + tap%5))*65];
        const float* ip1 = ip0 + 12*65;
        const ulonglong2* wt = wb + (size_t)tap*64*32;
#pragma unroll 8
        for (int ci = 0; ci < 64; ci++) {
            u64 v0 = pack2(ip0[ci]);
            u64 v1 = pack2(ip1[ci]);
            ulonglong2 q0 = wt[ci*32];
            ulonglong2 q1 = wt[ci*32 + 1];
            fma2(a0, v0, q0.x); fma2(a1, v0, q0.y);
            fma2(a2, v0, q1.x); fma2(a3, v0, q1.y);
            fma2(b0, v1, q0.x); fma2(b1, v1, q0.y);
            fma2(b2, v1, q1.x); fma2(b3, v1, q1.y);
        }
    }
    int gr = r0 + 2*pr, gc = c0 + pc;
    if (g_p2e[(gr*S2 + gc)*64]) {
        int pcell = (gr>>2)*S3 + (gc>>2);
        pool_scatter8(&g_p3e[pcell*128 + cog*8], a0, a1, a2, a3);
    }
    gr++;
    if (g_p2e[(gr*S2 + gc)*64]) {
        int pcell = (gr>>2)*S3 + (gc>>2);
        pool_scatter8(&g_p3e[pcell*128 + cog*8], b0, b1, b2, b3);
    }
}

// ---------------- K8: conv4 (128->256) dense over 36^2, f32x2, fused ELU + pool ----------------
// 512 threads: 16 cells (4x4 tile) x 32 cog-groups (8 couts each)
__global__ __launch_bounds__(512) void k_conv4(const float* __restrict__ w4) {
    __shared__ float in_s[64*128];         // 8x8 window x 128ch (broadcast reads, no pad)
    int r0 = blockIdx.y * 4, c0 = blockIdx.x * 4;
    for (int t = threadIdx.x; t < 64*128; t += 512) {
        int pos = t >> 7, ci = t & 127;
        int wr = pos >> 3, wc = pos & 7;
        int gr = r0 - 2 + wr, gc = c0 - 2 + wc;
        float v = 0.f;
        if ((unsigned)gr < (unsigned)S3 && (unsigned)gc < (unsigned)S3)
            v = g_p3v[(gr*S3 + gc)*128 + ci];
        in_s[pos*128 + ci] = v;
    }
    __syncthreads();
    int cog = threadIdx.x & 31, cell = threadIdx.x >> 5;
    int cr = cell >> 2, cc = cell & 3;
    u64 a0=0, a1=0, a2=0, a3=0;
    const ulonglong2* wb = (const ulonglong2*)w4 + cog*2;  // row = 64 ulonglong2
#pragma unroll 1
    for (int tap = 0; tap < 25; tap++) {
        const float* ip = &in_s[((cr + tap/5)*8 + (cc + tap%5))*128];
        const ulonglong2* wt = wb + (size_t)tap*128*64;
#pragma unroll 8
        for (int ci = 0; ci < 128; ci++) {
            u64 vv = pack2(ip[ci]);
            ulonglong2 q0 = wt[ci*64];
            ulonglong2 q1 = wt[ci*64 + 1];
            fma2(a0, vv, q0.x); fma2(a1, vv, q0.y);
            fma2(a2, vv, q1.x); fma2(a3, vv, q1.y);
        }
    }
    int gr = r0 + cr, gc = c0 + cc;
    if (g_p3e[(gr*S3 + gc)*128]) {
        int pc = (gr>>2)*S4 + (gc>>2);
        pool_scatter8(&g_p4e[pc*256 + cog*8], a0, a1, a2, a3);
    }
}

// ---------------- K10a: fc1 (20736 -> 32) + ELU. block j computes h[j] ----------------
__global__ __launch_bounds__(256) void k_fc1(const float* __restrict__ w,
                                             const float* __restrict__ b) {
    int j = blockIdx.x;                    // 0..31
    float s0 = 0.f, s1 = 0.f, s2 = 0.f, s3 = 0.f;
    for (int i = threadIdx.x; i < 20736; i += 1024) {
        int i0 = i, i1 = i + 256, i2 = i + 512, i3 = i + 768;
        { int c = i0/81, rem = i0 - c*81; s0 += g_p4v[rem*256 + c] * w[i0*32 + j]; }
        if (i1 < 20736) { int c = i1/81, rem = i1 - c*81; s1 += g_p4v[rem*256 + c] * w[i1*32 + j]; }
        if (i2 < 20736) { int c = i2/81, rem = i2 - c*81; s2 += g_p4v[rem*256 + c] * w[i2*32 + j]; }
        if (i3 < 20736) { int c = i3/81, rem = i3 - c*81; s3 += g_p4v[rem*256 + c] * w[i3*32 + j]; }
    }
    float s = (s0 + s1) + (s2 + s3);
    __shared__ float red[256];
    red[threadIdx.x] = s;
    __syncthreads();
    for (int o = 128; o > 0; o >>= 1) {
        if (threadIdx.x < o) red[threadIdx.x] += red[threadIdx.x + o];
        __syncthreads();
    }
    if (threadIdx.x == 0) {
        float z = red[0] + b[j];
        g_h[j] = z > 0.f ? z : expm1f(z);
    }
}

// ---------------- K10b: fc2 (32 -> 5) + softmax ----------------
__global__ void k_fc2(const float* __restrict__ w, const float* __restrict__ b,
                      float* __restrict__ out) {
    if (threadIdx.x == 0) {
        float lg[5];
#pragma unroll
        for (int t = 0; t < 5; t++) lg[t] = b[t];
        for (int j = 0; j < 32; j++) {
            float h = g_h[j];
#pragma unroll
            for (int t = 0; t < 5; t++) lg[t] += h * w[j*5 + t];
        }
        float m = lg[0];
#pragma unroll
        for (int t = 1; t < 5; t++) m = fmaxf(m, lg[t]);
        float e[5], sum = 0.f;
#pragma unroll
        for (int t = 0; t < 5; t++) { e[t] = expf(lg[t] - m); sum += e[t]; }
        float inv = 1.f / sum;
#pragma unroll
        for (int t = 0; t < 5; t++) out[t] = e[t] * inv;
    }
}

// ---------------- launch ----------------
extern "C" void kernel_launch(void* const* d_in, const int* in_sizes, int n_in,
                              void* d_out, int out_size) {
    const int*   coords = (const int*)  d_in[0];
    const float* feats  = (const float*)d_in[1];
    const float* w1     = (const float*)d_in[2];
    const float* w2     = (const float*)d_in[3];
    const float* w3     = (const float*)d_in[4];
    const float* w4     = (const float*)d_in[5];
    const float* fc1w   = (const float*)d_in[6];
    const float* fc1b   = (const float*)d_in[7];
    const float* fc2w   = (const float*)d_in[8];
    const float* fc2b   = (const float*)d_in[9];
    float* out = (float*)d_out;
    int P = in_sizes[1];                  // number of points

    k_zero<<<2048, 256>>>();
    k_scatter<<<(P + 255)/256, 256>>>(coords, feats, P);
    k_conv1<<<(P + 127)/128, 128>>>(coords, w1, P);
    k_clearpts<<<(P + 255)/256, 256>>>(coords, P);
    k_decode<<<(S1*S1*10 + 255)/256, 256>>>(0, S1*S1*10);
    k_list<<<(S1*S1 + 255)/256, 256>>>();
    k_conv2<<<(S1*S1 + 31)/32, 256>>>(w2);
    k_decode<<<(S2*S2*64 + 255)/256, 256>>>(1, S2*S2*64);
    k_conv3<<<dim3(S2/8, S2/8), 512>>>(w3);
    k_decode<<<(S3*S3*128 + 255)/256, 256>>>(2, S3*S3*128);
    k_conv4<<<dim3(S3/4, S3/4), 512>>>(w4);
    k_decode<<<(S4*S4*256 + 255)/256, 256>>>(3, S4*S4*256);
    k_fc1<<<32, 256>>>(fc1w, fc1b);
    k_fc2<<<1, 32>>>(fc2w, fc2b, out);
}